// round 2
// baseline (speedup 1.0000x reference)
#include <cuda_runtime.h>
#include <cstdint>

// Problem constants: x is (16384, 2048) fp32, angles (2048,) fp32, out (16384, 2048) fp32.
constexpr int NN = 2048;   // row length n
constexpr int T  = 256;    // threads per block
constexpr int E  = 8;      // elements per thread (T*E == NN)

// Scratch for precomputed cos/sin (device globals: no dynamic allocation allowed).
__device__ __align__(16) float g_c[NN];
__device__ __align__(16) float g_s[NN];

__global__ void prep_kernel(const float* __restrict__ ang) {
    int i = blockIdx.x * blockDim.x + threadIdx.x;
    if (i < NN) {
        float s, c;
        sincosf(ang[i], &s, &c);
        g_c[i] = c;
        g_s[i] = s;
    }
}

// y_row = G_0 (G_1 (... (G_{N-1} x_row))).
// Rotations applied k = N-1 .. 0; G_k acts on (k, (k+1)%N):
//   v[i] <- c*v[i] - s*v[j];  v[j] <- s*v[i] + c*v[j]
// Reduced to first-order affine recurrence on carry `prev` (see header comment
// in the launch function). Parallelized with an affine-map scan.
__global__ void __launch_bounds__(T) givens_kernel(const float* __restrict__ x,
                                                   float* __restrict__ y) {
    __shared__ float wtP[8], wtQ[8], wcarry[9];

    const int row = blockIdx.x;
    const float* __restrict__ xr = x + (size_t)row * NN;
    float* __restrict__ yr = y + (size_t)row * NN;
    const int t   = threadIdx.x;
    const int lid = t & 31;
    const int w   = t >> 5;
    const int lo  = t * E;

    // ---- coalesced float4 loads of the chunk + its c/s coefficients ----
    float xv[E], cc[E], ss[E];
    {
        float4 v0 = reinterpret_cast<const float4*>(xr + lo)[0];
        float4 v1 = reinterpret_cast<const float4*>(xr + lo)[1];
        xv[0] = v0.x; xv[1] = v0.y; xv[2] = v0.z; xv[3] = v0.w;
        xv[4] = v1.x; xv[5] = v1.y; xv[6] = v1.z; xv[7] = v1.w;
        float4 c0 = reinterpret_cast<const float4*>(g_c + lo)[0];
        float4 c1 = reinterpret_cast<const float4*>(g_c + lo)[1];
        cc[0] = c0.x; cc[1] = c0.y; cc[2] = c0.z; cc[3] = c0.w;
        cc[4] = c1.x; cc[5] = c1.y; cc[6] = c1.z; cc[7] = c1.w;
        float4 s0 = reinterpret_cast<const float4*>(g_s + lo)[0];
        float4 s1 = reinterpret_cast<const float4*>(g_s + lo)[1];
        ss[0] = s0.x; ss[1] = s0.y; ss[2] = s0.z; ss[3] = s0.w;
        ss[4] = s1.x; ss[5] = s1.y; ss[6] = s1.z; ss[7] = s1.w;
    }

    // Broadcast values (same address for all threads -> L1 broadcast).
    const float x0  = xr[0];
    const float xn1 = xr[NN - 1];
    const float cN  = g_c[NN - 1];
    const float sN  = g_s[NN - 1];
    const float seed = fmaf(cN, xn1, -sN * x0);    // prev_{N-1}
    if (t == 0) xv[0] = fmaf(sN, xn1, cN * x0);    // X_0 = updated x[0]

    // ---- per-chunk affine composition, downward over k (f_k(p) = -s_k p + c_k X_k) ----
    float P = 1.f, Q = 0.f;
#pragma unroll
    for (int m = E - 1; m >= 0; --m) {
        if (lo + m == NN - 1) continue;            // k = N-1 is the seed, not a step
        const float sk = ss[m];
        Q = fmaf(-sk, Q, cc[m] * xv[m]);
        P = -sk * P;
    }

    // ---- warp-level inclusive scan of affine maps.
    // "Earlier" in the scan = higher thread index (scan runs from k=N-2 down).
    // Received (higher lane) is the inner map; self is outer.
#pragma unroll
    for (int d = 1; d < 32; d <<= 1) {
        float p2 = __shfl_down_sync(0xffffffffu, P, d);
        float q2 = __shfl_down_sync(0xffffffffu, Q, d);
        if (lid + d < 32) {
            Q = fmaf(P, q2, Q);
            P = P * p2;
        }
    }
    if (lid == 0) { wtP[w] = P; wtQ[w] = Q; }      // warp total (covers whole warp)
    // warp-internal exclusive map = inclusive of lane+1 (identity at lane 31)
    float Pe = __shfl_down_sync(0xffffffffu, P, 1);
    float Qe = __shfl_down_sync(0xffffffffu, Q, 1);
    if (lid == 31) { Pe = 1.f; Qe = 0.f; }
    __syncthreads();

    // prefix over later warps (w2 > w), innermost = warp 7
    float Pp = 1.f, Qp = 0.f;
    for (int w2 = 7; w2 > w; --w2) {
        const float pt = wtP[w2], qt = wtQ[w2];
        Qp = fmaf(pt, Qp, qt);
        Pp = pt * Pp;
    }
    const float Pf = Pe * Pp;
    const float Qf = fmaf(Pe, Qp, Qe);
    float prev = fmaf(Pf, seed, Qf);               // carry entering this chunk's top

    // ---- replay: rv[m] = out[lo+m+1] ----
    float rv[E];
    rv[E - 1] = 0.f;                                // only thread T-1 skips m=E-1
#pragma unroll
    for (int m = E - 1; m >= 0; --m) {
        if (lo + m == NN - 1) continue;
        const float sk = ss[m], ck = cc[m], xm = xv[m];
        rv[m] = fmaf(sk, xm, ck * prev);
        prev  = fmaf(-sk, prev, ck * xm);
    }
    // prev is now prev_lo; for t==0 that equals out[0].

    // Rotate outputs by one element across threads so each thread holds
    // out[lo .. lo+7] (aligned for float4 stores). out[lo] comes from the
    // previous thread's rv[E-1] (shfl within warp, smem across warps).
    float carry = __shfl_up_sync(0xffffffffu, rv[E - 1], 1);
    if (lid == 31) wcarry[w + 1] = rv[E - 1];
    __syncthreads();
    if (lid == 0) carry = (w == 0) ? prev : wcarry[w];

    float4 o0, o1;
    o0.x = carry; o0.y = rv[0]; o0.z = rv[1]; o0.w = rv[2];
    o1.x = rv[3]; o1.y = rv[4]; o1.z = rv[5]; o1.w = rv[6];
    reinterpret_cast<float4*>(yr + lo)[0] = o0;
    reinterpret_cast<float4*>(yr + lo)[1] = o1;
}

extern "C" void kernel_launch(void* const* d_in, const int* in_sizes, int n_in,
                              void* d_out, int out_size) {
    const float* x   = (const float*)d_in[0];   // (B, N) fp32
    const float* ang = (const float*)d_in[1];   // (N,)  fp32
    float* y = (float*)d_out;                   // (B, N) fp32

    prep_kernel<<<(NN + 255) / 256, 256>>>(ang);

    const int rows = out_size / NN;             // B = 16384
    givens_kernel<<<rows, T>>>(x, y);
}